// round 15
// baseline (speedup 1.0000x reference)
#include <cuda_runtime.h>
#include <cuda_fp16.h>
#include <cstdint>

// Problem constants
#define NN   10000          // nodes
#define EE   20000          // edges (without self loops)
#define ETOT 30000          // edges + self loops
#define HH   12             // heads
#define CC   768            // per-head dim (== input feature dim)
#define HC   9216           // H*C
#define GGR  64             // graphs

#define MTILES 79           // ceil(10000/128)
#define NTILES 72           // 9216/128
#define KB16   48           // 768/16 k-blocks
#define FRAG_TILE_BYTES 196608

// ---------------- device scratch (static globals; no runtime alloc) --------
__device__ __half g_h16[(size_t)NN * HC];  // per-layer node features, fp16
__device__ float g_x2[NN * CC];            // layer-1 output / layer-2 input
__device__ float g_y[NN * CC];             // layer-2 output
__device__ uint4 g_Afrag[(size_t)MTILES * FRAG_TILE_BYTES / 16];
__device__ uint4 g_Bfrag[(size_t)NTILES * FRAG_TILE_BYTES / 16];
__device__ float g_Wsd[2][24 * CC];        // fused score weights, per layer
__device__ float g_s[2][NN * HH];          // alpha_src per node/head (atomic acc)
__device__ float g_d[2][NN * HH];          // alpha_dst per node/head (atomic acc)
__device__ int   g_indeg[NN];
__device__ int   g_rowptr[NN + 1];         // dst CSR
__device__ int   g_fill[NN];
__device__ int   g_ssrc[ETOT];             // src node per dst-CSR position
__device__ float g_pool[GGR * CC];
__device__ int   g_cnt[GGR];
__device__ int   g_gstart[GGR];

// ---------------- helpers ----------------------------------------------------
__device__ __forceinline__ uint32_t smem_u32(const void* p) {
    uint32_t a;
    asm("{ .reg .u64 t; cvta.to.shared.u64 t, %1; cvt.u32.u64 %0, t; }"
        : "=r"(a) : "l"(p));
    return a;
}

__device__ __forceinline__ unsigned pack2(float lo, float hi) {
    __half2 h = __floats2half2_rn(lo, hi);
    return *reinterpret_cast<unsigned*>(&h);
}

__device__ __forceinline__ void mma_fp16(float* d, const unsigned* a,
                                         unsigned b0, unsigned b1) {
    asm volatile(
        "mma.sync.aligned.m16n8k16.row.col.f32.f16.f16.f32 "
        "{%0,%1,%2,%3}, {%4,%5,%6,%7}, {%8,%9}, {%0,%1,%2,%3};\n"
        : "+f"(d[0]), "+f"(d[1]), "+f"(d[2]), "+f"(d[3])
        : "r"(a[0]), "r"(a[1]), "r"(a[2]), "r"(a[3]), "r"(b0), "r"(b1));
}

#define CP_ASYNC16(dst, src) \
    asm volatile("cp.async.cg.shared.global [%0], [%1], 16;" :: \
                 "r"(dst), "l"(src) : "memory")
#define CP_COMMIT() asm volatile("cp.async.commit_group;" ::: "memory")
#define CP_WAIT1()  asm volatile("cp.async.wait_group 1;" ::: "memory")
#define CP_WAIT0()  asm volatile("cp.async.wait_group 0;" ::: "memory")

#define LDS128(r0, r1, r2, r3, addr) \
    asm volatile("ld.shared.v4.b32 {%0,%1,%2,%3}, [%4];" \
                 : "=r"(r0), "=r"(r1), "=r"(r2), "=r"(r3) : "r"(addr))

// ---------------- zero / CSR build ------------------------------------------
__global__ void zero_build_kernel() {
    int i = blockIdx.x * blockDim.x + threadIdx.x;   // 480000 threads
    if (i < NN) { g_indeg[i] = 0; g_fill[i] = 0; }
    if (i < GGR) { g_cnt[i] = 0; g_gstart[i] = NN; }
    if (i < 2 * 24 * CC) ((float*)g_Wsd)[i] = 0.f;
    if (i < 2 * NN * HH) {
        ((float*)g_s)[i] = 0.f;
        ((float*)g_d)[i] = 0.f;
    }
}

__global__ void count_deg_kernel(const int* __restrict__ edge_index,
                                 const int* __restrict__ batch) {
    int e = blockIdx.x * blockDim.x + threadIdx.x;
    if (e < ETOT) {
        int dst = (e < EE) ? edge_index[EE + e] : (e - EE);
        atomicAdd(&g_indeg[dst], 1);
    }
    if (e < NN) {
        int b = batch[e];
        atomicMin(&g_gstart[b], e);
        atomicAdd(&g_cnt[b], 1);
    }
}

// fast exclusive scan: 10 elems/thread + shuffle scan (1024 threads)
__global__ void scan_kernel() {
    __shared__ int wsum[32];
    int t = threadIdx.x, lane = t & 31, wid = t >> 5;
    int base = t * 10;
    int loc[10];
    int s = 0;
#pragma unroll
    for (int i = 0; i < 10; i++) {
        int idx = base + i;
        int v = (idx < NN) ? g_indeg[idx] : 0;
        loc[i] = s;
        s += v;
    }
    int incl = s;
#pragma unroll
    for (int o = 1; o < 32; o <<= 1) {
        int x = __shfl_up_sync(0xffffffffu, incl, o);
        if (lane >= o) incl += x;
    }
    if (lane == 31) wsum[wid] = incl;
    __syncthreads();
    if (wid == 0) {
        int w = wsum[lane];
#pragma unroll
        for (int o = 1; o < 32; o <<= 1) {
            int x = __shfl_up_sync(0xffffffffu, w, o);
            if (lane >= o) w += x;
        }
        wsum[lane] = w;
    }
    __syncthreads();
    int off = incl - s + (wid ? wsum[wid - 1] : 0);
#pragma unroll
    for (int i = 0; i < 10; i++) {
        int idx = base + i;
        if (idx <= NN) g_rowptr[idx] = off + loc[i];
    }
}

__global__ void fill_csr_kernel(const int* __restrict__ edge_index) {
    int e = blockIdx.x * blockDim.x + threadIdx.x;
    if (e >= ETOT) return;
    int src = (e < EE) ? edge_index[e]      : (e - EE);
    int dst = (e < EE) ? edge_index[EE + e] : (e - EE);
    int pd = g_rowptr[dst] + atomicAdd(&g_fill[dst], 1);
    g_ssrc[pd] = src;
}

// ---------------- prep_A + fused node scores ---------------------------------
// packs fp16 A fragments AND accumulates s/d[n][h] = sum_k A[n][k]*Wsd[j][k]
__global__ __launch_bounds__(256)
void prep_A_kernel(const float* __restrict__ src, int M, int layer) {
    __shared__ float st[128 * 68];       // 128 rows x 64 k, pitch 68
    __shared__ float wsl[24 * 64];       // Wsd slice for this kgrp (6 KB)
    int tid = threadIdx.x, lane = tid & 31, wid = tid >> 5;
    int mtile = blockIdx.x, kgrp = blockIdx.y;
#pragma unroll
    for (int i = 0; i < 8; i++) {
        int idx = tid + i * 256;
        int row = idx >> 4, c4 = idx & 15;
        int m = mtile * 128 + row;
        float4 v = make_float4(0.f, 0.f, 0.f, 0.f);
        if (m < M) v = *(const float4*)&src[(size_t)m * CC + kgrp * 64 + c4 * 4];
        *(float4*)&st[row * 68 + c4 * 4] = v;
    }
    // Wsd slice: wsl[j][k] = Wsd[layer][j][kgrp*64+k], 1536 floats
#pragma unroll
    for (int i = 0; i < 6; i++) {
        int idx = tid + i * 256;
        int j = idx >> 6, k = idx & 63;
        wsl[idx] = g_Wsd[layer][j * CC + kgrp * 64 + k];
    }
    __syncthreads();

    // --- fused node scores: thread owns row r = tid>>1, half jh = tid&1
    {
        int r  = tid >> 1;
        int jh = tid & 1;                 // 0 -> s (j 0..11), 1 -> d (j 12..23)
        int node = mtile * 128 + r;
        float acc[HH];
#pragma unroll
        for (int h = 0; h < HH; h++) acc[h] = 0.f;
        const float4* st4  = (const float4*)&st[r * 68];
#pragma unroll
        for (int k4 = 0; k4 < 16; k4++) {
            float4 a = st4[k4];
#pragma unroll
            for (int h = 0; h < HH; h++) {
                const float4 w = *(const float4*)&wsl[(jh * 12 + h) * 64 + k4 * 4];
                acc[h] += a.x * w.x + a.y * w.y + a.z * w.z + a.w * w.w;
            }
        }
        if (node < M) {
            float* dstp = jh ? &g_d[layer][node * HH] : &g_s[layer][node * HH];
#pragma unroll
            for (int h = 0; h < HH; h++) atomicAdd(&dstp[h], acc[h]);
        }
    }

    // --- fragment pack (st unchanged)
    int g = lane >> 2, tg = lane & 3;
#pragma unroll
    for (int t = 0; t < 4; t++) {
        int fb  = wid * 4 + t;
        int kbl = fb & 3, m16 = fb >> 2;
        int r0 = m16 * 16 + g, r1 = r0 + 8;
        int k0 = kbl * 16 + 2 * tg;
        uint4 o;
        o.x = pack2(st[r0 * 68 + k0],     st[r0 * 68 + k0 + 1]);
        o.y = pack2(st[r1 * 68 + k0],     st[r1 * 68 + k0 + 1]);
        o.z = pack2(st[r0 * 68 + k0 + 8], st[r0 * 68 + k0 + 9]);
        o.w = pack2(st[r1 * 68 + k0 + 8], st[r1 * 68 + k0 + 9]);
        g_Afrag[(size_t)(mtile * KB16 + kgrp * 4 + kbl) * 256 + m16 * 32 + lane] = o;
    }
}

// ---------------- prep_B + fused score-weight partials (Wsd) -----------------
__global__ __launch_bounds__(256)
void prep_B_kernel(const float* __restrict__ W, const float* __restrict__ a_src,
                   const float* __restrict__ a_dst, int wsbuf) {
    __shared__ float st[64 * 132];
    __shared__ float red[2][64][4];
    int tid = threadIdx.x, lane = tid & 31, wid = tid >> 5;
    int ntile = blockIdx.x, kgrp = blockIdx.y;
#pragma unroll
    for (int i = 0; i < 8; i++) {
        int idx = tid + i * 256;
        int row = idx >> 5, c4 = idx & 31;
        float4 v = *(const float4*)&W[(size_t)(kgrp * 64 + row) * HC +
                                      ntile * 128 + c4 * 4];
        *(float4*)&st[row * 132 + c4 * 4] = v;
    }
    __syncthreads();

    // fused Wsd partials: this tile covers head h, cols c0..c0+127
    {
        int h  = (ntile * 128) / CC;
        int c0 = (ntile * 128) % CC;
        int k  = tid & 63, q = tid >> 6;          // q in 0..3, 32 cols each
        float psrc = 0.f, pdst = 0.f;
        const float* as = &a_src[h * CC + c0 + q * 32];
        const float* ad = &a_dst[h * CC + c0 + q * 32];
#pragma unroll
        for (int ci = 0; ci < 32; ci++) {
            float w = st[k * 132 + q * 32 + ci];
            psrc += w * as[ci];
            pdst += w * ad[ci];
        }
        red[0][k][q] = psrc;
        red[1][k][q] = pdst;
        __syncthreads();
        if (tid < 128) {
            int j = tid >> 6, kk = tid & 63;
            float v = red[j][kk][0] + red[j][kk][1] + red[j][kk][2] + red[j][kk][3];
            atomicAdd(&g_Wsd[wsbuf][(j ? 12 + h : h) * CC + kgrp * 64 + kk], v);
        }
    }

    // fragment pack (st unchanged)
    int g = lane >> 2, tg = lane & 3;
#pragma unroll
    for (int t = 0; t < 4; t++) {
        int fb  = wid * 4 + t;
        int kbl = fb & 3, n16 = fb >> 2;
        int k0 = kbl * 16 + 2 * tg;
        int ne = n16 * 16 + g, no = ne + 8;
        uint4 o;
        o.x = pack2(st[k0 * 132 + ne],       st[(k0 + 1) * 132 + ne]);
        o.y = pack2(st[(k0 + 8) * 132 + ne], st[(k0 + 9) * 132 + ne]);
        o.z = pack2(st[k0 * 132 + no],       st[(k0 + 1) * 132 + no]);
        o.w = pack2(st[(k0 + 8) * 132 + no], st[(k0 + 9) * 132 + no]);
        g_Bfrag[(size_t)(ntile * KB16 + kgrp * 4 + kbl) * 256 + n16 * 32 + lane] = o;
    }
}

// ---------------- fp16 fragment GEMM (fp16 output) ---------------------------
#define NCHK 12
#define STAGE_BYTES 32768

__global__ __launch_bounds__(256)
void frag_gemm_kernel(__half* __restrict__ Hm, int M) {
    extern __shared__ char smem[];
    const uint32_t sbase = smem_u32(smem);
    const int tid = threadIdx.x, wid = tid >> 5, lane = tid & 31;
    const int mtile = blockIdx.y, ntile = blockIdx.x;
    const char* Abase = (const char*)g_Afrag + (size_t)mtile * FRAG_TILE_BYTES;
    const char* Bbase = (const char*)g_Bfrag + (size_t)ntile * FRAG_TILE_BYTES;

    const int g = lane >> 2, tg = lane & 3;
    const int mb16 = (wid & 3) * 2;
    const int nb16 = (wid >> 2) * 4;

    float acc[2][8][4];
#pragma unroll
    for (int i = 0; i < 2; i++)
#pragma unroll
        for (int j = 0; j < 8; j++)
#pragma unroll
            for (int q = 0; q < 4; q++) acc[i][j][q] = 0.f;

#define STAGE_CP(buf, chunk)                                              \
    {                                                                     \
        const char* as = Abase + (size_t)(chunk) * 16384 + tid * 16;      \
        const char* bs = Bbase + (size_t)(chunk) * 16384 + tid * 16;      \
        uint32_t ad = sbase + (buf) * STAGE_BYTES + tid * 16;             \
        uint32_t bd = ad + 16384;                                         \
        _Pragma("unroll")                                                 \
        for (int i = 0; i < 4; i++) {                                     \
            CP_ASYNC16(ad + i * 4096, as + (size_t)i * 4096);             \
            CP_ASYNC16(bd + i * 4096, bs + (size_t)i * 4096);             \
        }                                                                 \
        CP_COMMIT();                                                      \
    }

    STAGE_CP(0, 0)
    STAGE_CP(1, 1)

    for (int it = 0; it < NCHK; it++) {
        if (it + 2 < NCHK) { CP_WAIT1(); } else { CP_WAIT0(); }
        __syncthreads();
        uint32_t sa = sbase + (it & 1) * STAGE_BYTES;
        uint32_t sb = sa + 16384;
#pragma unroll
        for (int kbl = 0; kbl < 4; kbl++) {
            unsigned af[2][4], bf[4][4];
#pragma unroll
            for (int mi = 0; mi < 2; mi++) {
                uint32_t a = sa + (uint32_t)(((kbl * 8 + mb16 + mi) * 32 + lane) * 16);
                LDS128(af[mi][0], af[mi][1], af[mi][2], af[mi][3], a);
            }
#pragma unroll
            for (int j = 0; j < 4; j++) {
                uint32_t a = sb + (uint32_t)(((kbl * 8 + nb16 + j) * 32 + lane) * 16);
                LDS128(bf[j][0], bf[j][1], bf[j][2], bf[j][3], a);
            }
#pragma unroll
            for (int mi = 0; mi < 2; mi++)
#pragma unroll
                for (int j = 0; j < 4; j++) {
                    mma_fp16(acc[mi][2 * j],     af[mi], bf[j][0], bf[j][1]);
                    mma_fp16(acc[mi][2 * j + 1], af[mi], bf[j][2], bf[j][3]);
                }
        }
        __syncthreads();
        if (it + 2 < NCHK) STAGE_CP(it & 1, it + 2)
    }

    const int brow = mtile * 128, bcol = ntile * 128;
    const int wm = (wid & 3) * 32, wn = (wid >> 2) * 64;
#pragma unroll
    for (int mi = 0; mi < 2; mi++) {
#pragma unroll
        for (int nj = 0; nj < 8; nj++) {
            int r = brow + wm + mi * 16 + g;
            int c = bcol + wn + nj * 8 + 2 * tg;
            if (r < M)
                *(__half2*)&Hm[(size_t)r * HC + c] =
                    __floats2half2_rn(acc[mi][nj][0], acc[mi][nj][1]);
            if (r + 8 < M)
                *(__half2*)&Hm[(size_t)(r + 8) * HC + c] =
                    __floats2half2_rn(acc[mi][nj][2], acc[mi][nj][3]);
        }
    }
#undef STAGE_CP
}

// ---------------- gather aggregation + inline softmax (sync-free edges) ------
__global__ __launch_bounds__(256)
void gather_agg_kernel(const float* __restrict__ bias, float* __restrict__ out,
                       int layer) {
    __shared__ float sd[HH], smx[HH], sinv[HH];
    int n   = blockIdx.x;
    int tid = threadIdx.x;
    int r0 = g_rowptr[n], r1 = g_rowptr[n + 1];

    if (tid < HH) {
        float dn = g_d[layer][n * HH + tid];
        sd[tid] = dn;
        float mx = -1e30f;
        for (int p = r0; p < r1; p++) {
            float v = g_s[layer][g_ssrc[p] * HH + tid] + dn;
            v = (v > 0.f) ? v : 0.2f * v;
            mx = fmaxf(mx, v);
        }
        float sum = 0.f;
        for (int p = r0; p < r1; p++) {
            float v = g_s[layer][g_ssrc[p] * HH + tid] + dn;
            v = (v > 0.f) ? v : 0.2f * v;
            sum += __expf(v - mx);
        }
        smx[tid]  = mx;
        sinv[tid] = 1.f / ((float)HH * (sum + 1e-16f));
    }
    __syncthreads();                     // the ONLY block sync

    float a0 = bias[tid], a1 = bias[tid + 256], a2 = bias[tid + 512];
    for (int p = r0; p < r1; p++) {
        int src = g_ssrc[p];
        // per-thread alphas (broadcast g_s loads; redundant exp on purpose)
        const float* sp = &g_s[layer][src * HH];
        float al[HH];
#pragma unroll
        for (int h = 0; h < HH; h++) {
            float v = __ldg(&sp[h]) + sd[h];
            v = (v > 0.f) ? v : 0.2f * v;
            al[h] = __expf(v - smx[h]) * sinv[h];
        }
        // direct gmem feature reads: coalesced, no staging, no syncs
        const __half* hp = &g_h16[(size_t)src * HC];
        float v0 = 0.f, v1 = 0.f, v2 = 0.f;
#pragma unroll
        for (int h = 0; h < HH; h++) {
            float a = al[h];
            v0 += a * __half2float(__ldg(&hp[h * CC + tid]));
            v1 += a * __half2float(__ldg(&hp[h * CC + tid + 256]));
            v2 += a * __half2float(__ldg(&hp[h * CC + tid + 512]));
        }
        a0 += v0; a1 += v1; a2 += v2;
    }
    out[(size_t)n * CC + tid]       = a0;
    out[(size_t)n * CC + tid + 256] = a1;
    out[(size_t)n * CC + tid + 512] = a2;
}

// ---------------- pooling: contiguous segment sum (batch sorted) -------------
__global__ __launch_bounds__(192)
void pool_sum_kernel(const float* __restrict__ xin) {
    int gid = blockIdx.x;
    int c4  = threadIdx.x;               // float4 column 0..191
    int start = g_gstart[gid], cnt = g_cnt[gid];
    const float4* base = (const float4*)xin + (size_t)start * (CC / 4) + c4;
    float4 s = make_float4(0.f, 0.f, 0.f, 0.f);
    int i = 0;
    for (; i + 2 <= cnt; i += 2) {
        float4 v0 = __ldg(base + (size_t)i * (CC / 4));
        float4 v1 = __ldg(base + (size_t)(i + 1) * (CC / 4));
        s.x += v0.x + v1.x; s.y += v0.y + v1.y;
        s.z += v0.z + v1.z; s.w += v0.w + v1.w;
    }
    if (i < cnt) {
        float4 v0 = __ldg(base + (size_t)i * (CC / 4));
        s.x += v0.x; s.y += v0.y; s.z += v0.z; s.w += v0.w;
    }
    *(float4*)&g_pool[gid * CC + c4 * 4] = s;
}

// ---------------- final MLP (block per graph) -------------------------------
__global__ __launch_bounds__(128)
void mlp_kernel(const float* __restrict__ w1, const float* __restrict__ b1,
                const float* __restrict__ w2, const float* __restrict__ b2,
                float* __restrict__ out) {
    int gid = blockIdx.x;
    int tid = threadIdx.x;
    __shared__ float gv[CC];
    __shared__ float z[128];
    float invc = 1.0f / fmaxf((float)g_cnt[gid], 1.0f);
    for (int c = tid; c < CC; c += 128) gv[c] = g_pool[gid * CC + c] * invc;
    __syncthreads();
    float acc = b1[tid];
    for (int k = 0; k < CC; k++) acc += gv[k] * w1[k * 128 + tid];
    z[tid] = fmaxf(acc, 0.f);
    __syncthreads();
    if (tid < 4) {
        float o = b2[tid];
        for (int j = 0; j < 128; j++) o += z[j] * w2[j * 4 + tid];
        out[gid * 4 + tid] = o;
    }
}

// ---------------- launcher ---------------------------------------------------
extern "C" void kernel_launch(void* const* d_in, const int* in_sizes, int n_in,
                              void* d_out, int out_size) {
    const float* x        = (const float*)d_in[0];
    const int*   eidx     = (const int*)  d_in[1];
    const int*   batch    = (const int*)  d_in[2];
    const float* W1       = (const float*)d_in[3];
    const float* a_src1   = (const float*)d_in[4];
    const float* a_dst1   = (const float*)d_in[5];
    const float* b1       = (const float*)d_in[6];
    const float* W2       = (const float*)d_in[7];
    const float* a_src2   = (const float*)d_in[8];
    const float* a_dst2   = (const float*)d_in[9];
    const float* b2       = (const float*)d_in[10];
    const float* mlp_w1   = (const float*)d_in[11];
    const float* mlp_b1   = (const float*)d_in[12];
    const float* mlp_w2   = (const float*)d_in[13];
    const float* mlp_b2   = (const float*)d_in[14];
    float* out = (float*)d_out;

    __half* p_h;
    float *p_x2, *p_y;
    cudaGetSymbolAddress((void**)&p_h,  g_h16);
    cudaGetSymbolAddress((void**)&p_x2, g_x2);
    cudaGetSymbolAddress((void**)&p_y,  g_y);

    const int gemm_smem = 2 * STAGE_BYTES;     // 65536
    cudaFuncSetAttribute(frag_gemm_kernel,
                         cudaFuncAttributeMaxDynamicSharedMemorySize, gemm_smem);

    // --- zero + CSR build + graph segments ---
    zero_build_kernel<<<(2 * NN * HH + 255) / 256, 256>>>();
    count_deg_kernel<<<(ETOT + 255) / 256, 256>>>(eidx, batch);
    scan_kernel<<<1, 1024>>>();
    fill_csr_kernel<<<(ETOT + 255) / 256, 256>>>(eidx);

    dim3 pa_grid(MTILES, 12);
    dim3 pb_grid(NTILES, 12);
    dim3 ggrid(NTILES, MTILES);

    // --- GAT layer 1 ---
    prep_B_kernel<<<pb_grid, 256>>>(W1, a_src1, a_dst1, 0);   // Wsd[0] ready
    prep_A_kernel<<<pa_grid, 256>>>(x, NN, 0);                // frags + s/d[0]
    frag_gemm_kernel<<<ggrid, 256, gemm_smem>>>(p_h, NN);
    gather_agg_kernel<<<NN, 256>>>(b1, p_x2, 0);              // inline softmax

    // --- GAT layer 2 ---
    prep_B_kernel<<<pb_grid, 256>>>(W2, a_src2, a_dst2, 1);   // Wsd[1] ready
    prep_A_kernel<<<pa_grid, 256>>>(p_x2, NN, 1);             // frags + s/d[1]
    frag_gemm_kernel<<<ggrid, 256, gemm_smem>>>(p_h, NN);
    gather_agg_kernel<<<NN, 256>>>(b2, p_y, 1);

    // --- pooling + MLP ---
    pool_sum_kernel<<<GGR, 192>>>(p_y);
    mlp_kernel<<<GGR, 128>>>(mlp_w1, mlp_b1, mlp_w2, mlp_b2, out);
}

// round 16
// speedup vs baseline: 1.1355x; 1.1355x over previous
#include <cuda_runtime.h>
#include <cuda_fp16.h>
#include <cstdint>

// Problem constants
#define NN   10000          // nodes
#define EE   20000          // edges (without self loops)
#define ETOT 30000          // edges + self loops
#define HH   12             // heads
#define CC   768            // per-head dim (== input feature dim)
#define HC   9216           // H*C
#define GGR  64             // graphs

#define MTILES 79           // ceil(10000/128)
#define NTILES 72           // 9216/128
#define KB16   48           // 768/16 k-blocks
#define FRAG_TILE_BYTES 196608

// ---------------- device scratch (static globals; no runtime alloc) --------
__device__ __half g_h16[(size_t)NN * HC];  // per-layer node features, fp16
__device__ float g_x2[NN * CC];            // layer-1 output / layer-2 input
__device__ float g_y[NN * CC];             // layer-2 output
__device__ uint4 g_Afrag[(size_t)MTILES * FRAG_TILE_BYTES / 16];
__device__ uint4 g_Bfrag[(size_t)NTILES * FRAG_TILE_BYTES / 16];
__device__ float g_Wsd[2][24 * CC];        // fused score weights, per layer
__device__ float g_s[2][NN * HH];          // alpha_src per node/head (atomic acc)
__device__ float g_d[2][NN * HH];          // alpha_dst per node/head (atomic acc)
__device__ int   g_indeg[NN];
__device__ int   g_rowptr[NN + 1];         // dst CSR
__device__ int   g_fill[NN];
__device__ int   g_ssrc[ETOT];             // src node per dst-CSR position
__device__ float g_pool[GGR * CC];
__device__ int   g_cnt[GGR];
__device__ int   g_gstart[GGR];

// ---------------- helpers ----------------------------------------------------
__device__ __forceinline__ uint32_t smem_u32(const void* p) {
    uint32_t a;
    asm("{ .reg .u64 t; cvta.to.shared.u64 t, %1; cvt.u32.u64 %0, t; }"
        : "=r"(a) : "l"(p));
    return a;
}

__device__ __forceinline__ unsigned pack2(float lo, float hi) {
    __half2 h = __floats2half2_rn(lo, hi);
    return *reinterpret_cast<unsigned*>(&h);
}

__device__ __forceinline__ void mma_fp16(float* d, const unsigned* a,
                                         unsigned b0, unsigned b1) {
    asm volatile(
        "mma.sync.aligned.m16n8k16.row.col.f32.f16.f16.f32 "
        "{%0,%1,%2,%3}, {%4,%5,%6,%7}, {%8,%9}, {%0,%1,%2,%3};\n"
        : "+f"(d[0]), "+f"(d[1]), "+f"(d[2]), "+f"(d[3])
        : "r"(a[0]), "r"(a[1]), "r"(a[2]), "r"(a[3]), "r"(b0), "r"(b1));
}

#define CP_ASYNC16(dst, src) \
    asm volatile("cp.async.cg.shared.global [%0], [%1], 16;" :: \
                 "r"(dst), "l"(src) : "memory")
#define CP_COMMIT() asm volatile("cp.async.commit_group;" ::: "memory")
#define CP_WAIT1()  asm volatile("cp.async.wait_group 1;" ::: "memory")
#define CP_WAIT0()  asm volatile("cp.async.wait_group 0;" ::: "memory")

#define LDS128(r0, r1, r2, r3, addr) \
    asm volatile("ld.shared.v4.b32 {%0,%1,%2,%3}, [%4];" \
                 : "=r"(r0), "=r"(r1), "=r"(r2), "=r"(r3) : "r"(addr))

// ---------------- zero / CSR build ------------------------------------------
__global__ void zero_build_kernel() {
    int i = blockIdx.x * blockDim.x + threadIdx.x;
    if (i < NN) { g_indeg[i] = 0; g_fill[i] = 0; }
    if (i < GGR) { g_cnt[i] = 0; g_gstart[i] = NN; }
    if (i < 2 * 24 * CC) ((float*)g_Wsd)[i] = 0.f;
    if (i < 2 * NN * HH) {
        ((float*)g_s)[i] = 0.f;
        ((float*)g_d)[i] = 0.f;
    }
}

__global__ void count_deg_kernel(const int* __restrict__ edge_index,
                                 const int* __restrict__ batch) {
    int e = blockIdx.x * blockDim.x + threadIdx.x;
    if (e < ETOT) {
        int dst = (e < EE) ? edge_index[EE + e] : (e - EE);
        atomicAdd(&g_indeg[dst], 1);
    }
    if (e < NN) {
        int b = batch[e];
        atomicMin(&g_gstart[b], e);
        atomicAdd(&g_cnt[b], 1);
    }
}

// fast exclusive scan: 10 elems/thread + shuffle scan (1024 threads)
__global__ void scan_kernel() {
    __shared__ int wsum[32];
    int t = threadIdx.x, lane = t & 31, wid = t >> 5;
    int base = t * 10;
    int loc[10];
    int s = 0;
#pragma unroll
    for (int i = 0; i < 10; i++) {
        int idx = base + i;
        int v = (idx < NN) ? g_indeg[idx] : 0;
        loc[i] = s;
        s += v;
    }
    int incl = s;
#pragma unroll
    for (int o = 1; o < 32; o <<= 1) {
        int x = __shfl_up_sync(0xffffffffu, incl, o);
        if (lane >= o) incl += x;
    }
    if (lane == 31) wsum[wid] = incl;
    __syncthreads();
    if (wid == 0) {
        int w = wsum[lane];
#pragma unroll
        for (int o = 1; o < 32; o <<= 1) {
            int x = __shfl_up_sync(0xffffffffu, w, o);
            if (lane >= o) w += x;
        }
        wsum[lane] = w;
    }
    __syncthreads();
    int off = incl - s + (wid ? wsum[wid - 1] : 0);
#pragma unroll
    for (int i = 0; i < 10; i++) {
        int idx = base + i;
        if (idx <= NN) g_rowptr[idx] = off + loc[i];
    }
}

__global__ void fill_csr_kernel(const int* __restrict__ edge_index) {
    int e = blockIdx.x * blockDim.x + threadIdx.x;
    if (e >= ETOT) return;
    int src = (e < EE) ? edge_index[e]      : (e - EE);
    int dst = (e < EE) ? edge_index[EE + e] : (e - EE);
    int pd = g_rowptr[dst] + atomicAdd(&g_fill[dst], 1);
    g_ssrc[pd] = src;
}

// ---------------- prep_A + fused node scores ---------------------------------
__global__ __launch_bounds__(256)
void prep_A_kernel(const float* __restrict__ src, int M, int layer) {
    __shared__ float st[128 * 68];       // 128 rows x 64 k, pitch 68
    __shared__ float wsl[24 * 64];       // Wsd slice for this kgrp (6 KB)
    int tid = threadIdx.x, lane = tid & 31, wid = tid >> 5;
    int mtile = blockIdx.x, kgrp = blockIdx.y;
#pragma unroll
    for (int i = 0; i < 8; i++) {
        int idx = tid + i * 256;
        int row = idx >> 4, c4 = idx & 15;
        int m = mtile * 128 + row;
        float4 v = make_float4(0.f, 0.f, 0.f, 0.f);
        if (m < M) v = *(const float4*)&src[(size_t)m * CC + kgrp * 64 + c4 * 4];
        *(float4*)&st[row * 68 + c4 * 4] = v;
    }
#pragma unroll
    for (int i = 0; i < 6; i++) {
        int idx = tid + i * 256;
        int j = idx >> 6, k = idx & 63;
        wsl[idx] = g_Wsd[layer][j * CC + kgrp * 64 + k];
    }
    __syncthreads();

    // fused node scores: thread owns row r = tid>>1, half jh = tid&1
    {
        int r  = tid >> 1;
        int jh = tid & 1;
        int node = mtile * 128 + r;
        float acc[HH];
#pragma unroll
        for (int h = 0; h < HH; h++) acc[h] = 0.f;
        const float4* st4  = (const float4*)&st[r * 68];
#pragma unroll
        for (int k4 = 0; k4 < 16; k4++) {
            float4 a = st4[k4];
#pragma unroll
            for (int h = 0; h < HH; h++) {
                const float4 w = *(const float4*)&wsl[(jh * 12 + h) * 64 + k4 * 4];
                acc[h] += a.x * w.x + a.y * w.y + a.z * w.z + a.w * w.w;
            }
        }
        if (node < M) {
            float* dstp = jh ? &g_d[layer][node * HH] : &g_s[layer][node * HH];
#pragma unroll
            for (int h = 0; h < HH; h++) atomicAdd(&dstp[h], acc[h]);
        }
    }

    // fragment pack
    int g = lane >> 2, tg = lane & 3;
#pragma unroll
    for (int t = 0; t < 4; t++) {
        int fb  = wid * 4 + t;
        int kbl = fb & 3, m16 = fb >> 2;
        int r0 = m16 * 16 + g, r1 = r0 + 8;
        int k0 = kbl * 16 + 2 * tg;
        uint4 o;
        o.x = pack2(st[r0 * 68 + k0],     st[r0 * 68 + k0 + 1]);
        o.y = pack2(st[r1 * 68 + k0],     st[r1 * 68 + k0 + 1]);
        o.z = pack2(st[r0 * 68 + k0 + 8], st[r0 * 68 + k0 + 9]);
        o.w = pack2(st[r1 * 68 + k0 + 8], st[r1 * 68 + k0 + 9]);
        g_Afrag[(size_t)(mtile * KB16 + kgrp * 4 + kbl) * 256 + m16 * 32 + lane] = o;
    }
}

// ---------------- prep_B + fused score-weight partials (Wsd) -----------------
__global__ __launch_bounds__(256)
void prep_B_kernel(const float* __restrict__ W, const float* __restrict__ a_src,
                   const float* __restrict__ a_dst, int wsbuf) {
    __shared__ float st[64 * 132];
    __shared__ float red[2][64][4];
    int tid = threadIdx.x, lane = tid & 31, wid = tid >> 5;
    int ntile = blockIdx.x, kgrp = blockIdx.y;
#pragma unroll
    for (int i = 0; i < 8; i++) {
        int idx = tid + i * 256;
        int row = idx >> 5, c4 = idx & 31;
        float4 v = *(const float4*)&W[(size_t)(kgrp * 64 + row) * HC +
                                      ntile * 128 + c4 * 4];
        *(float4*)&st[row * 132 + c4 * 4] = v;
    }
    __syncthreads();

    {
        int h  = (ntile * 128) / CC;
        int c0 = (ntile * 128) % CC;
        int k  = tid & 63, q = tid >> 6;
        float psrc = 0.f, pdst = 0.f;
        const float* as = &a_src[h * CC + c0 + q * 32];
        const float* ad = &a_dst[h * CC + c0 + q * 32];
#pragma unroll
        for (int ci = 0; ci < 32; ci++) {
            float w = st[k * 132 + q * 32 + ci];
            psrc += w * as[ci];
            pdst += w * ad[ci];
        }
        red[0][k][q] = psrc;
        red[1][k][q] = pdst;
        __syncthreads();
        if (tid < 128) {
            int j = tid >> 6, kk = tid & 63;
            float v = red[j][kk][0] + red[j][kk][1] + red[j][kk][2] + red[j][kk][3];
            atomicAdd(&g_Wsd[wsbuf][(j ? 12 + h : h) * CC + kgrp * 64 + kk], v);
        }
    }

    int g = lane >> 2, tg = lane & 3;
#pragma unroll
    for (int t = 0; t < 4; t++) {
        int fb  = wid * 4 + t;
        int kbl = fb & 3, n16 = fb >> 2;
        int k0 = kbl * 16 + 2 * tg;
        int ne = n16 * 16 + g, no = ne + 8;
        uint4 o;
        o.x = pack2(st[k0 * 132 + ne],       st[(k0 + 1) * 132 + ne]);
        o.y = pack2(st[(k0 + 8) * 132 + ne], st[(k0 + 9) * 132 + ne]);
        o.z = pack2(st[k0 * 132 + no],       st[(k0 + 1) * 132 + no]);
        o.w = pack2(st[(k0 + 8) * 132 + no], st[(k0 + 9) * 132 + no]);
        g_Bfrag[(size_t)(ntile * KB16 + kgrp * 4 + kbl) * 256 + n16 * 32 + lane] = o;
    }
}

// ---------------- fp16 fragment GEMM (fp16 output) ---------------------------
#define NCHK 12
#define STAGE_BYTES 32768

__global__ __launch_bounds__(256)
void frag_gemm_kernel(__half* __restrict__ Hm, int M) {
    extern __shared__ char smem[];
    const uint32_t sbase = smem_u32(smem);
    const int tid = threadIdx.x, wid = tid >> 5, lane = tid & 31;
    const int mtile = blockIdx.y, ntile = blockIdx.x;
    const char* Abase = (const char*)g_Afrag + (size_t)mtile * FRAG_TILE_BYTES;
    const char* Bbase = (const char*)g_Bfrag + (size_t)ntile * FRAG_TILE_BYTES;

    const int g = lane >> 2, tg = lane & 3;
    const int mb16 = (wid & 3) * 2;
    const int nb16 = (wid >> 2) * 4;

    float acc[2][8][4];
#pragma unroll
    for (int i = 0; i < 2; i++)
#pragma unroll
        for (int j = 0; j < 8; j++)
#pragma unroll
            for (int q = 0; q < 4; q++) acc[i][j][q] = 0.f;

#define STAGE_CP(buf, chunk)                                              \
    {                                                                     \
        const char* as = Abase + (size_t)(chunk) * 16384 + tid * 16;      \
        const char* bs = Bbase + (size_t)(chunk) * 16384 + tid * 16;      \
        uint32_t ad = sbase + (buf) * STAGE_BYTES + tid * 16;             \
        uint32_t bd = ad + 16384;                                         \
        _Pragma("unroll")                                                 \
        for (int i = 0; i < 4; i++) {                                     \
            CP_ASYNC16(ad + i * 4096, as + (size_t)i * 4096);             \
            CP_ASYNC16(bd + i * 4096, bs + (size_t)i * 4096);             \
        }                                                                 \
        CP_COMMIT();                                                      \
    }

    STAGE_CP(0, 0)
    STAGE_CP(1, 1)

    for (int it = 0; it < NCHK; it++) {
        if (it + 2 < NCHK) { CP_WAIT1(); } else { CP_WAIT0(); }
        __syncthreads();
        uint32_t sa = sbase + (it & 1) * STAGE_BYTES;
        uint32_t sb = sa + 16384;
#pragma unroll
        for (int kbl = 0; kbl < 4; kbl++) {
            unsigned af[2][4], bf[4][4];
#pragma unroll
            for (int mi = 0; mi < 2; mi++) {
                uint32_t a = sa + (uint32_t)(((kbl * 8 + mb16 + mi) * 32 + lane) * 16);
                LDS128(af[mi][0], af[mi][1], af[mi][2], af[mi][3], a);
            }
#pragma unroll
            for (int j = 0; j < 4; j++) {
                uint32_t a = sb + (uint32_t)(((kbl * 8 + nb16 + j) * 32 + lane) * 16);
                LDS128(bf[j][0], bf[j][1], bf[j][2], bf[j][3], a);
            }
#pragma unroll
            for (int mi = 0; mi < 2; mi++)
#pragma unroll
                for (int j = 0; j < 4; j++) {
                    mma_fp16(acc[mi][2 * j],     af[mi], bf[j][0], bf[j][1]);
                    mma_fp16(acc[mi][2 * j + 1], af[mi], bf[j][2], bf[j][3]);
                }
        }
        __syncthreads();
        if (it + 2 < NCHK) STAGE_CP(it & 1, it + 2)
    }

    const int brow = mtile * 128, bcol = ntile * 128;
    const int wm = (wid & 3) * 32, wn = (wid >> 2) * 64;
#pragma unroll
    for (int mi = 0; mi < 2; mi++) {
#pragma unroll
        for (int nj = 0; nj < 8; nj++) {
            int r = brow + wm + mi * 16 + g;
            int c = bcol + wn + nj * 8 + 2 * tg;
            if (r < M)
                *(__half2*)&Hm[(size_t)r * HC + c] =
                    __floats2half2_rn(acc[mi][nj][0], acc[mi][nj][1]);
            if (r + 8 < M)
                *(__half2*)&Hm[(size_t)(r + 8) * HC + c] =
                    __floats2half2_rn(acc[mi][nj][2], acc[mi][nj][3]);
        }
    }
#undef STAGE_CP
}

// ---------------- gather aggregation: inline softmax + cp.async pipeline -----
__global__ __launch_bounds__(256)
void gather_agg_kernel(const float* __restrict__ bias, float* __restrict__ out,
                       int layer) {
    __shared__ __half rowh[2][HC];       // 2 x 18 KB double buffer
    __shared__ float sd[HH], smx[HH], sinv[HH];
    __shared__ float sal[2][HH];
    int n   = blockIdx.x;
    int tid = threadIdx.x;
    int r0 = g_rowptr[n], r1 = g_rowptr[n + 1];
    uint32_t sb0 = smem_u32(&rowh[0][0]);
    uint32_t sb1 = smem_u32(&rowh[1][0]);

    // per-head softmax stats (12 threads; others proceed to prefetch)
    if (tid < HH) {
        float dn = g_d[layer][n * HH + tid];
        sd[tid] = dn;
        float mx = -1e30f;
        for (int p = r0; p < r1; p++) {
            float v = g_s[layer][g_ssrc[p] * HH + tid] + dn;
            v = (v > 0.f) ? v : 0.2f * v;
            mx = fmaxf(mx, v);
        }
        float sum = 0.f;
        for (int p = r0; p < r1; p++) {
            float v = g_s[layer][g_ssrc[p] * HH + tid] + dn;
            v = (v > 0.f) ? v : 0.2f * v;
            sum += __expf(v - mx);
        }
        smx[tid]  = mx;
        sinv[tid] = 1.f / ((float)HH * (sum + 1e-16f));
        // alpha of first edge
        {
            float v = g_s[layer][g_ssrc[r0] * HH + tid] + dn;
            v = (v > 0.f) ? v : 0.2f * v;
            sal[0][tid] = __expf(v - mx) * sinv[tid];
        }
    }

    // prefetch first row into buffer 0
    {
        const char* hp = (const char*)&g_h16[(size_t)g_ssrc[r0] * HC];
#pragma unroll
        for (int i = 0; i < 5; i++) {
            int idx = tid + i * 256;
            if (idx < 1152) CP_ASYNC16(sb0 + idx * 16, hp + idx * 16);
        }
        CP_COMMIT();
    }

    float a0 = bias[tid], a1 = bias[tid + 256], a2 = bias[tid + 512];
    for (int p = r0; p < r1; p++) {
        int cur = (p - r0) & 1;
        if (p + 1 < r1) {
            // prefetch next row + its alpha while current loads drain
            const char* hp = (const char*)&g_h16[(size_t)g_ssrc[p + 1] * HC];
            uint32_t dstb = cur ? sb0 : sb1;
#pragma unroll
            for (int i = 0; i < 5; i++) {
                int idx = tid + i * 256;
                if (idx < 1152) CP_ASYNC16(dstb + idx * 16, hp + idx * 16);
            }
            CP_COMMIT();
            if (tid < HH) {
                float v = g_s[layer][g_ssrc[p + 1] * HH + tid] + sd[tid];
                v = (v > 0.f) ? v : 0.2f * v;
                sal[cur ^ 1][tid] = __expf(v - smx[tid]) * sinv[tid];
            }
            CP_WAIT1();
        } else {
            CP_WAIT0();
        }
        __syncthreads();                  // current buffer + sal[cur] visible
        const __half* rp = rowh[cur];
        float al[HH];
#pragma unroll
        for (int h = 0; h < HH; h++) al[h] = sal[cur][h];
        float v0 = 0.f, v1 = 0.f, v2 = 0.f;
#pragma unroll
        for (int h = 0; h < HH; h++) {
            float a = al[h];
            v0 += a * __half2float(rp[h * CC + tid]);
            v1 += a * __half2float(rp[h * CC + tid + 256]);
            v2 += a * __half2float(rp[h * CC + tid + 512]);
        }
        a0 += v0; a1 += v1; a2 += v2;
        __syncthreads();                  // reads done before next overwrite
    }
    out[(size_t)n * CC + tid]       = a0;
    out[(size_t)n * CC + tid + 256] = a1;
    out[(size_t)n * CC + tid + 512] = a2;
}

// ---------------- pooling: contiguous segment sum (batch sorted) -------------
__global__ __launch_bounds__(192)
void pool_sum_kernel(const float* __restrict__ xin) {
    int gid = blockIdx.x;
    int c4  = threadIdx.x;
    int start = g_gstart[gid], cnt = g_cnt[gid];
    const float4* base = (const float4*)xin + (size_t)start * (CC / 4) + c4;
    float4 s = make_float4(0.f, 0.f, 0.f, 0.f);
    int i = 0;
    for (; i + 2 <= cnt; i += 2) {
        float4 v0 = __ldg(base + (size_t)i * (CC / 4));
        float4 v1 = __ldg(base + (size_t)(i + 1) * (CC / 4));
        s.x += v0.x + v1.x; s.y += v0.y + v1.y;
        s.z += v0.z + v1.z; s.w += v0.w + v1.w;
    }
    if (i < cnt) {
        float4 v0 = __ldg(base + (size_t)i * (CC / 4));
        s.x += v0.x; s.y += v0.y; s.z += v0.z; s.w += v0.w;
    }
    *(float4*)&g_pool[gid * CC + c4 * 4] = s;
}

// ---------------- final MLP (block per graph) -------------------------------
__global__ __launch_bounds__(128)
void mlp_kernel(const float* __restrict__ w1, const float* __restrict__ b1,
                const float* __restrict__ w2, const float* __restrict__ b2,
                float* __restrict__ out) {
    int gid = blockIdx.x;
    int tid = threadIdx.x;
    __shared__ float gv[CC];
    __shared__ float z[128];
    float invc = 1.0f / fmaxf((float)g_cnt[gid], 1.0f);
    for (int c = tid; c < CC; c += 128) gv[c] = g_pool[gid * CC + c] * invc;
    __syncthreads();
    float acc = b1[tid];
    for (int k = 0; k < CC; k++) acc += gv[k] * w1[k * 128 + tid];
    z[tid] = fmaxf(acc, 0.f);
    __syncthreads();
    if (tid < 4) {
        float o = b2[tid];
        for (int j = 0; j < 128; j++) o += z[j] * w2[j * 4 + tid];
        out[gid * 4 + tid] = o;
    }
}

// ---------------- launcher ---------------------------------------------------
extern "C" void kernel_launch(void* const* d_in, const int* in_sizes, int n_in,
                              void* d_out, int out_size) {
    const float* x        = (const float*)d_in[0];
    const int*   eidx     = (const int*)  d_in[1];
    const int*   batch    = (const int*)  d_in[2];
    const float* W1       = (const float*)d_in[3];
    const float* a_src1   = (const float*)d_in[4];
    const float* a_dst1   = (const float*)d_in[5];
    const float* b1       = (const float*)d_in[6];
    const float* W2       = (const float*)d_in[7];
    const float* a_src2   = (const float*)d_in[8];
    const float* a_dst2   = (const float*)d_in[9];
    const float* b2       = (const float*)d_in[10];
    const float* mlp_w1   = (const float*)d_in[11];
    const float* mlp_b1   = (const float*)d_in[12];
    const float* mlp_w2   = (const float*)d_in[13];
    const float* mlp_b2   = (const float*)d_in[14];
    float* out = (float*)d_out;

    __half* p_h;
    float *p_x2, *p_y;
    cudaGetSymbolAddress((void**)&p_h,  g_h16);
    cudaGetSymbolAddress((void**)&p_x2, g_x2);
    cudaGetSymbolAddress((void**)&p_y,  g_y);

    const int gemm_smem = 2 * STAGE_BYTES;     // 65536
    cudaFuncSetAttribute(frag_gemm_kernel,
                         cudaFuncAttributeMaxDynamicSharedMemorySize, gemm_smem);

    // --- zero + CSR build + graph segments ---
    zero_build_kernel<<<(2 * NN * HH + 255) / 256, 256>>>();
    count_deg_kernel<<<(ETOT + 255) / 256, 256>>>(eidx, batch);
    scan_kernel<<<1, 1024>>>();
    fill_csr_kernel<<<(ETOT + 255) / 256, 256>>>(eidx);

    dim3 pa_grid(MTILES, 12);
    dim3 pb_grid(NTILES, 12);
    dim3 ggrid(NTILES, MTILES);

    // --- GAT layer 1 ---
    prep_B_kernel<<<pb_grid, 256>>>(W1, a_src1, a_dst1, 0);   // Wsd[0] ready
    prep_A_kernel<<<pa_grid, 256>>>(x, NN, 0);                // frags + s/d[0]
    frag_gemm_kernel<<<ggrid, 256, gemm_smem>>>(p_h, NN);
    gather_agg_kernel<<<NN, 256>>>(b1, p_x2, 0);              // inline softmax

    // --- GAT layer 2 ---
    prep_B_kernel<<<pb_grid, 256>>>(W2, a_src2, a_dst2, 1);   // Wsd[1] ready
    prep_A_kernel<<<pa_grid, 256>>>(p_x2, NN, 1);             // frags + s/d[1]
    frag_gemm_kernel<<<ggrid, 256, gemm_smem>>>(p_h, NN);
    gather_agg_kernel<<<NN, 256>>>(b2, p_y, 1);

    // --- pooling + MLP ---
    pool_sum_kernel<<<GGR, 192>>>(p_y);
    mlp_kernel<<<GGR, 128>>>(mlp_w1, mlp_b1, mlp_w2, mlp_b2, out);
}